// round 8
// baseline (speedup 1.0000x reference)
#include <cuda_runtime.h>
#include <math.h>

#define HEADS   8
#define DHEAD   32
#define HS      48
#define WS      48
#define HWs     (HS * WS)          // 2304
#define WIN     7
#define RAD     3
#define KN      (WIN * WIN)        // 49
#define TILE    16                 // 16x16 pixel tile, 2 rows per thread
#define NTHR    128
#define HALO    (TILE + 2 * RAD)   // 22
#define HP2     24                 // row stride in float2 elems (2-row offset = 16 banks)
#define HALO_PIX (HALO * HALO)     // 484

#define KPAIRS  16                 // all 32 channels staged as float2 pairs
#define VCP     4                  // pairs per V chunk (8 scalar channels)
#define SK_SIZE (KPAIRS * HALO * HP2)              // float2 elems
#define SV_SIZE (VCP * HALO * HP2)
#define SMEM_BYTES ((SK_SIZE + 2 * SV_SIZE) * (int)sizeof(float2))  // 101376

typedef unsigned long long ull;

__device__ __forceinline__ ull pack2(float lo, float hi) {
    ull r;
    asm("mov.b64 %0, {%1, %2};" : "=l"(r) : "f"(lo), "f"(hi));
    return r;
}
__device__ __forceinline__ void unpack2(ull v, float& lo, float& hi) {
    asm("mov.b64 {%0, %1}, %2;" : "=f"(lo), "=f"(hi) : "l"(v));
}
__device__ __forceinline__ void ffma2(ull& acc, ull a, ull b) {
    asm("fma.rn.f32x2 %0, %1, %2, %3;" : "=l"(acc) : "l"(a), "l"(b), "l"(acc));
}
__device__ __forceinline__ ull add2(ull a, ull b) {
    ull r;
    asm("add.rn.f32x2 %0, %1, %2;" : "=l"(r) : "l"(a), "l"(b));
    return r;
}

// Load NP channel-pairs of a halo tile into smem (pixel-outer, pair-inner: high MLP).
template<int NP>
__device__ __forceinline__ void load_halo(const float* __restrict__ plane0,
                                          float2* __restrict__ dst,
                                          int tid, int tileX0, int tileY0)
{
    #pragma unroll
    for (int ps = 0; ps < HALO_PIX; ps += NTHR) {
        const int p = ps + tid;
        if (p < HALO_PIX) {
            const int hy = p / HALO;
            const int hx = p - hy * HALO;
            const int gy = tileY0 + hy - RAD;
            const int gx = tileX0 + hx - RAD;
            const bool valid = (gy >= 0) & (gy < HS) & (gx >= 0) & (gx < WS);
            const int src = min(max(gy, 0), HS - 1) * WS + min(max(gx, 0), WS - 1);
            #pragma unroll
            for (int pp = 0; pp < NP; pp++) {
                float a = __ldg(plane0 + (2 * pp + 0) * HWs + src);
                float b = __ldg(plane0 + (2 * pp + 1) * HWs + src);
                dst[pp * (HALO * HP2) + hy * HP2 + hx] =
                    valid ? make_float2(a, b) : make_float2(0.0f, 0.0f);
            }
        }
    }
}

// Pass-1 score accumulation over K channel-pairs [P0, P1).
template<int P0, int P1>
__device__ __forceinline__ void pass1(const float2* __restrict__ sK,
                                      const float* __restrict__ qp,
                                      ull* __restrict__ s0, ull* __restrict__ s1,
                                      int typ, int tx, int pix0, int pix1)
{
    ull qa0 = pack2(qp[(2 * P0) * HWs + pix0], qp[(2 * P0 + 1) * HWs + pix0]);
    ull qa1 = pack2(qp[(2 * P0) * HWs + pix1], qp[(2 * P0 + 1) * HWs + pix1]);
    #pragma unroll 1
    for (int cpi = P0; cpi < P1; cpi++) {
        ull qb0 = 0, qb1 = 0;
        if (cpi + 1 < P1) {
            const int cn = 2 * (cpi + 1);
            qb0 = pack2(qp[cn * HWs + pix0], qp[(cn + 1) * HWs + pix0]);
            qb1 = pack2(qp[cn * HWs + pix1], qp[(cn + 1) * HWs + pix1]);
        }
        const float2* kb = sK + cpi * (HALO * HP2) + (2 * typ) * HP2 + tx;
        #pragma unroll
        for (int r = 0; r < 8; r++) {
            const ull* wr = (const ull*)(kb + r * HP2);
            ull w0 = wr[0], w1 = wr[1], w2 = wr[2], w3 = wr[3],
                w4 = wr[4], w5 = wr[5], w6 = wr[6];
            if (r < 7) {   // compile-time
                const int b = r * 7;
                ffma2(s0[b + 0], qa0, w0);
                ffma2(s0[b + 1], qa0, w1);
                ffma2(s0[b + 2], qa0, w2);
                ffma2(s0[b + 3], qa0, w3);
                ffma2(s0[b + 4], qa0, w4);
                ffma2(s0[b + 5], qa0, w5);
                ffma2(s0[b + 6], qa0, w6);
            }
            if (r > 0) {   // compile-time
                const int b = (r - 1) * 7;
                ffma2(s1[b + 0], qa1, w0);
                ffma2(s1[b + 1], qa1, w1);
                ffma2(s1[b + 2], qa1, w2);
                ffma2(s1[b + 3], qa1, w3);
                ffma2(s1[b + 4], qa1, w4);
                ffma2(s1[b + 5], qa1, w5);
                ffma2(s1[b + 6], qa1, w6);
            }
        }
        qa0 = qb0; qa1 = qb1;
    }
}

// Pass-2: one V chunk (VCP pairs) -> 8 output channels starting at cBase.
__device__ __forceinline__ void vchunk(const float2* __restrict__ buf,
                                       float* __restrict__ og, int cBase,
                                       const ull* __restrict__ s0,
                                       const ull* __restrict__ s1,
                                       int typ, int tx, int pix0, int pix1)
{
    #pragma unroll 1
    for (int pp = 0; pp < VCP; pp++) {
        const float2* vb = buf + pp * (HALO * HP2) + (2 * typ) * HP2 + tx;
        ull a0 = 0, a1 = 0, a2 = 0, a3 = 0;
        ull b0 = 0, b1 = 0, b2 = 0, b3 = 0;
        #pragma unroll
        for (int r = 0; r < 8; r++) {
            const ull* wr = (const ull*)(vb + r * HP2);
            ull w0 = wr[0], w1 = wr[1], w2 = wr[2], w3 = wr[3],
                w4 = wr[4], w5 = wr[5], w6 = wr[6];
            if (r < 7) {
                const int n = r * 7;
                ffma2(a0, s0[n + 0], w0);
                ffma2(a1, s0[n + 1], w1);
                ffma2(a2, s0[n + 2], w2);
                ffma2(a3, s0[n + 3], w3);
                ffma2(a0, s0[n + 4], w4);
                ffma2(a1, s0[n + 5], w5);
                ffma2(a2, s0[n + 6], w6);
            }
            if (r > 0) {
                const int n = (r - 1) * 7;
                ffma2(b0, s1[n + 0], w0);
                ffma2(b1, s1[n + 1], w1);
                ffma2(b2, s1[n + 2], w2);
                ffma2(b3, s1[n + 3], w3);
                ffma2(b0, s1[n + 4], w4);
                ffma2(b1, s1[n + 5], w5);
                ffma2(b2, s1[n + 6], w6);
            }
        }
        ull ta = add2(add2(a0, a1), add2(a2, a3));
        ull tb = add2(add2(b0, b1), add2(b2, b3));
        float oa_e, oa_o, ob_e, ob_o;
        unpack2(ta, oa_e, oa_o);
        unpack2(tb, ob_e, ob_o);
        const int ce = cBase + 2 * pp;
        og[ce * HWs + pix0]       = oa_e;
        og[(ce + 1) * HWs + pix0] = oa_o;
        og[ce * HWs + pix1]       = ob_e;
        og[(ce + 1) * HWs + pix1] = ob_o;
    }
}

__global__ __launch_bounds__(NTHR, 2)
void natten2d_kernel(const float* __restrict__ q,
                     const float* __restrict__ k,
                     const float* __restrict__ v,
                     float* __restrict__ out)
{
    extern __shared__ float2 sm[];
    float2* sK  = sm;                       // 16 pairs full K halo (67.6 KB)
    float2* sV0 = sm + SK_SIZE;             // V chunk buffer A (16.9 KB)
    float2* sV1 = sm + SK_SIZE + SV_SIZE;   // V chunk buffer B (16.9 KB)

    const int tid = threadIdx.x;
    const int tx  = tid & 15;
    const int typ = tid >> 4;               // rows {2typ, 2typ+1}

    const int tileX0 = blockIdx.x * TILE;
    const int tileY0 = blockIdx.y * TILE;
    const size_t base = (size_t)blockIdx.z * DHEAD * HWs;

    const float* qp = q + base;
    const float* kp = k + base;
    const float* vp = v + base;
    float* op = out + base;

    const int x    = tileX0 + tx;
    const int y0   = tileY0 + 2 * typ;
    const int y1   = y0 + 1;
    const int pix0 = y0 * WS + x;
    const int pix1 = pix0 + WS;

    // ---- issue ALL K halo loads + V chunk0 loads up front (max MLP) ----
    load_halo<KPAIRS>(kp, sK, tid, tileX0, tileY0);
    load_halo<VCP>(vp, sV0, tid, tileX0, tileY0);          // ch 0..7
    __syncthreads();

    // ---- pass 1 (no intermediate syncs; V chunk1 load hidden mid-pass) ----
    ull s0[KN], s1[KN];
    #pragma unroll
    for (int n = 0; n < KN; n++) { s0[n] = 0ULL; s1[n] = 0ULL; }

    pass1<0, 8>(sK, qp, s0, s1, typ, tx, pix0, pix1);
    load_halo<VCP>(vp + 8 * HWs, sV1, tid, tileX0, tileY0); // ch 8..15 (overlaps below)
    pass1<8, KPAIRS>(sK, qp, s0, s1, typ, tx, pix0, pix1);

    // ---- reduce packed pairs + mask + scale + softmax ----
    const float scale = 0.17677669529663687f; // 1/sqrt(32)
    float p0s[KN], p1s[KN];
    float m0 = -1e30f, m1 = -1e30f;
    #pragma unroll
    for (int n = 0; n < KN; n++) {
        float lo, hi;
        unpack2(s0[n], lo, hi);
        float v0 = lo + hi;
        unpack2(s1[n], lo, hi);
        float v1 = lo + hi;
        const int dy = n / WIN - RAD;
        const int dx = n % WIN - RAD;
        const int gx = x + dx;
        const bool vx = (gx >= 0) & (gx < WS);
        const int gy0 = y0 + dy;
        const int gy1 = y1 + dy;
        const bool ok0 = vx & (gy0 >= 0) & (gy0 < HS);
        const bool ok1 = vx & (gy1 >= 0) & (gy1 < HS);
        p0s[n] = ok0 ? v0 * scale : -1e30f;
        p1s[n] = ok1 ? v1 * scale : -1e30f;
        m0 = fmaxf(m0, p0s[n]);
        m1 = fmaxf(m1, p1s[n]);
    }
    float sum0 = 0.0f, sum1 = 0.0f;
    #pragma unroll
    for (int n = 0; n < KN; n++) {
        p0s[n] = __expf(p0s[n] - m0);
        p1s[n] = __expf(p1s[n] - m1);
        sum0 += p0s[n];
        sum1 += p1s[n];
    }
    const float inv0 = 1.0f / sum0;
    const float inv1 = 1.0f / sum1;
    #pragma unroll
    for (int n = 0; n < KN; n++) {
        float a = p0s[n] * inv0;
        float b = p1s[n] * inv1;
        s0[n] = pack2(a, a);
        s1[n] = pack2(b, b);
    }

    // ---- pass 2: 4 chunks, double-buffered; loads overlap compute ----
    // chunk0 (sV0) stores were covered by the first __syncthreads().
    vchunk(sV0, op, 0, s0, s1, typ, tx, pix0, pix1);          // ch 0..7
    __syncthreads();                                          // frees sV0, drains V1 stores
    load_halo<VCP>(vp + 16 * HWs, sV0, tid, tileX0, tileY0);  // ch 16..23 (overlaps below)
    vchunk(sV1, op, 8, s0, s1, typ, tx, pix0, pix1);          // ch 8..15
    __syncthreads();                                          // frees sV1, drains V2 stores
    load_halo<VCP>(vp + 24 * HWs, sV1, tid, tileX0, tileY0);  // ch 24..31 (overlaps below)
    vchunk(sV0, op, 16, s0, s1, typ, tx, pix0, pix1);         // ch 16..23
    __syncthreads();                                          // drains V3 stores
    vchunk(sV1, op, 24, s0, s1, typ, tx, pix0, pix1);         // ch 24..31
}

extern "C" void kernel_launch(void* const* d_in, const int* in_sizes, int n_in,
                              void* d_out, int out_size)
{
    const float* q = (const float*)d_in[0];
    const float* k = (const float*)d_in[1];
    const float* v = (const float*)d_in[2];
    float* o = (float*)d_out;

    // Device-function attribute set: not an allocation, not a stream op —
    // safe under graph capture. Called idempotently every launch.
    cudaFuncSetAttribute(natten2d_kernel,
                         cudaFuncAttributeMaxDynamicSharedMemorySize, SMEM_BYTES);

    const int B = in_sizes[0] / (HEADS * DHEAD * HWs); // 4
    dim3 grid(WS / TILE, HS / TILE, B * HEADS);        // (3, 3, 32) = 288
    dim3 block(NTHR);                                  // 128 linear
    natten2d_kernel<<<grid, block, SMEM_BYTES>>>(q, k, v, o);
}

// round 9
// speedup vs baseline: 1.3604x; 1.3604x over previous
#include <cuda_runtime.h>
#include <stdint.h>

#define HEADS   8
#define DHEAD   32
#define HS      48
#define WS      48
#define HWs     (HS * WS)          // 2304
#define WIN     7
#define RAD     3
#define KN      (WIN * WIN)        // 49
#define TILE    16                 // 16x16 pixel tile, 2 rows per thread
#define NTHR    128
#define HALO    (TILE + 2 * RAD)   // 22
#define HP2     24                 // row stride in float2 elems
#define HALO_PIX (HALO * HALO)     // 484

#define CPAIR   4                  // channel-pairs per chunk (8 scalar channels)
#define CHUNK_F2 (CPAIR * HALO * HP2)        // 2112 float2 per buffer
#define SMEM_BYTES (4 * CHUNK_F2 * 8)        // 67584 B (4-buffer ring)

typedef unsigned long long ull;

__device__ __forceinline__ ull pack2(float lo, float hi) {
    ull r;
    asm("mov.b64 %0, {%1, %2};" : "=l"(r) : "f"(lo), "f"(hi));
    return r;
}
__device__ __forceinline__ void unpack2(ull v, float& lo, float& hi) {
    asm("mov.b64 {%0, %1}, %2;" : "=f"(lo), "=f"(hi) : "l"(v));
}
__device__ __forceinline__ void ffma2(ull& acc, ull a, ull b) {
    asm("fma.rn.f32x2 %0, %1, %2, %3;" : "=l"(acc) : "l"(a), "l"(b), "l"(acc));
}
__device__ __forceinline__ ull add2(ull a, ull b) {
    ull r;
    asm("add.rn.f32x2 %0, %1, %2;" : "=l"(r) : "l"(a), "l"(b));
    return r;
}

__device__ __forceinline__ void cp4(uint32_t dst, const float* src) {
    asm volatile("cp.async.ca.shared.global [%0], [%1], 4;" :: "r"(dst), "l"(src));
}
#define CP_COMMIT()  asm volatile("cp.async.commit_group;" ::: "memory")
#define CP_WAIT(N)   asm volatile("cp.async.wait_group %0;" :: "n"(N) : "memory")

// Issue one 8-channel halo chunk as cp.async (zero register residency).
// Invalid halo cells get STS-zero instead (per-thread divergence, legal).
__device__ __forceinline__ void load_chunk(const float* __restrict__ plane0,
                                           uint32_t sbase,
                                           int tid, int tileX0, int tileY0)
{
    #pragma unroll
    for (int ps = 0; ps < HALO_PIX; ps += NTHR) {
        const int p = ps + tid;
        if (p < HALO_PIX) {
            const int hy = p / HALO;
            const int hx = p - hy * HALO;
            const int gy = tileY0 + hy - RAD;
            const int gx = tileX0 + hx - RAD;
            const bool valid = (gy >= 0) & (gy < HS) & (gx >= 0) & (gx < WS);
            const uint32_t db = sbase + (uint32_t)(hy * HP2 + hx) * 8u;
            if (valid) {
                const float* sp = plane0 + gy * WS + gx;
                #pragma unroll
                for (int c = 0; c < 2 * CPAIR; c++)
                    cp4(db + (uint32_t)(c >> 1) * (HALO * HP2 * 8) + (c & 1) * 4,
                        sp + c * HWs);
            } else {
                #pragma unroll
                for (int c = 0; c < 2 * CPAIR; c++) {
                    uint32_t a = db + (uint32_t)(c >> 1) * (HALO * HP2 * 8) + (c & 1) * 4;
                    asm volatile("st.shared.b32 [%0], %1;" :: "r"(a), "r"(0u));
                }
            }
        }
    }
    CP_COMMIT();
}

// Pass-1 score accumulation over one chunk (4 pairs), q pipelined.
__device__ __forceinline__ void pass1_chunk(const float2* __restrict__ buf,
                                            const float* __restrict__ qp, int cBase,
                                            ull* __restrict__ s0, ull* __restrict__ s1,
                                            int typ, int tx, int pix0, int pix1)
{
    ull qa0 = pack2(qp[cBase * HWs + pix0], qp[(cBase + 1) * HWs + pix0]);
    ull qa1 = pack2(qp[cBase * HWs + pix1], qp[(cBase + 1) * HWs + pix1]);
    #pragma unroll 1
    for (int pp = 0; pp < CPAIR; pp++) {
        ull qb0 = 0, qb1 = 0;
        if (pp + 1 < CPAIR) {
            const int cn = cBase + 2 * (pp + 1);
            qb0 = pack2(qp[cn * HWs + pix0], qp[(cn + 1) * HWs + pix0]);
            qb1 = pack2(qp[cn * HWs + pix1], qp[(cn + 1) * HWs + pix1]);
        }
        const float2* kb = buf + pp * (HALO * HP2) + (2 * typ) * HP2 + tx;
        #pragma unroll
        for (int r = 0; r < 8; r++) {
            const ull* wr = (const ull*)(kb + r * HP2);
            ull w0 = wr[0], w1 = wr[1], w2 = wr[2], w3 = wr[3],
                w4 = wr[4], w5 = wr[5], w6 = wr[6];
            if (r < 7) {   // compile-time
                const int b = r * 7;
                ffma2(s0[b + 0], qa0, w0);
                ffma2(s0[b + 1], qa0, w1);
                ffma2(s0[b + 2], qa0, w2);
                ffma2(s0[b + 3], qa0, w3);
                ffma2(s0[b + 4], qa0, w4);
                ffma2(s0[b + 5], qa0, w5);
                ffma2(s0[b + 6], qa0, w6);
            }
            if (r > 0) {   // compile-time
                const int b = (r - 1) * 7;
                ffma2(s1[b + 0], qa1, w0);
                ffma2(s1[b + 1], qa1, w1);
                ffma2(s1[b + 2], qa1, w2);
                ffma2(s1[b + 3], qa1, w3);
                ffma2(s1[b + 4], qa1, w4);
                ffma2(s1[b + 5], qa1, w5);
                ffma2(s1[b + 6], qa1, w6);
            }
        }
        qa0 = qb0; qa1 = qb1;
    }
}

// Pass-2: one chunk (4 pairs) -> 8 output channels starting at cBase.
__device__ __forceinline__ void vchunk(const float2* __restrict__ buf,
                                       float* __restrict__ og, int cBase,
                                       const ull* __restrict__ s0,
                                       const ull* __restrict__ s1,
                                       int typ, int tx, int pix0, int pix1)
{
    #pragma unroll 1
    for (int pp = 0; pp < CPAIR; pp++) {
        const float2* vb = buf + pp * (HALO * HP2) + (2 * typ) * HP2 + tx;
        ull a0 = 0, a1 = 0, a2 = 0, a3 = 0;
        ull b0 = 0, b1 = 0, b2 = 0, b3 = 0;
        #pragma unroll
        for (int r = 0; r < 8; r++) {
            const ull* wr = (const ull*)(vb + r * HP2);
            ull w0 = wr[0], w1 = wr[1], w2 = wr[2], w3 = wr[3],
                w4 = wr[4], w5 = wr[5], w6 = wr[6];
            if (r < 7) {
                const int n = r * 7;
                ffma2(a0, s0[n + 0], w0);
                ffma2(a1, s0[n + 1], w1);
                ffma2(a2, s0[n + 2], w2);
                ffma2(a3, s0[n + 3], w3);
                ffma2(a0, s0[n + 4], w4);
                ffma2(a1, s0[n + 5], w5);
                ffma2(a2, s0[n + 6], w6);
            }
            if (r > 0) {
                const int n = (r - 1) * 7;
                ffma2(b0, s1[n + 0], w0);
                ffma2(b1, s1[n + 1], w1);
                ffma2(b2, s1[n + 2], w2);
                ffma2(b3, s1[n + 3], w3);
                ffma2(b0, s1[n + 4], w4);
                ffma2(b1, s1[n + 5], w5);
                ffma2(b2, s1[n + 6], w6);
            }
        }
        ull ta = add2(add2(a0, a1), add2(a2, a3));
        ull tb = add2(add2(b0, b1), add2(b2, b3));
        float oa_e, oa_o, ob_e, ob_o;
        unpack2(ta, oa_e, oa_o);
        unpack2(tb, ob_e, ob_o);
        const int ce = cBase + 2 * pp;
        og[ce * HWs + pix0]       = oa_e;
        og[(ce + 1) * HWs + pix0] = oa_o;
        og[ce * HWs + pix1]       = ob_e;
        og[(ce + 1) * HWs + pix1] = ob_o;
    }
}

__global__ __launch_bounds__(NTHR, 2)
void natten2d_kernel(const float* __restrict__ q,
                     const float* __restrict__ k,
                     const float* __restrict__ v,
                     float* __restrict__ out)
{
    extern __shared__ float2 sm[];
    float2* buf0 = sm;
    float2* buf1 = sm + 1 * CHUNK_F2;
    float2* buf2 = sm + 2 * CHUNK_F2;
    float2* buf3 = sm + 3 * CHUNK_F2;
    const uint32_t sb0 = (uint32_t)__cvta_generic_to_shared(buf0);
    const uint32_t sb1 = (uint32_t)__cvta_generic_to_shared(buf1);
    const uint32_t sb2 = (uint32_t)__cvta_generic_to_shared(buf2);
    const uint32_t sb3 = (uint32_t)__cvta_generic_to_shared(buf3);

    const int tid = threadIdx.x;
    const int tx  = tid & 15;
    const int typ = tid >> 4;               // rows {2typ, 2typ+1}

    const int tileX0 = blockIdx.x * TILE;
    const int tileY0 = blockIdx.y * TILE;
    const size_t base = (size_t)blockIdx.z * DHEAD * HWs;

    const float* qp = q + base;
    const float* kp = k + base;
    const float* vp = v + base;
    float* op = out + base;

    const int x    = tileX0 + tx;
    const int y0   = tileY0 + 2 * typ;
    const int y1   = y0 + 1;
    const int pix0 = y0 * WS + x;
    const int pix1 = pix0 + WS;

    // ---- issue K0..K3 as async groups g0..g3 (no register residency) ----
    load_chunk(kp,            sb0, tid, tileX0, tileY0);
    load_chunk(kp +  8 * HWs, sb1, tid, tileX0, tileY0);
    load_chunk(kp + 16 * HWs, sb2, tid, tileX0, tileY0);
    load_chunk(kp + 24 * HWs, sb3, tid, tileX0, tileY0);

    ull s0[KN], s1[KN];
    #pragma unroll
    for (int n = 0; n < KN; n++) { s0[n] = 0ULL; s1[n] = 0ULL; }

    // ---- pass 1, chunk-pipelined; V issues slot in as K buffers free ----
    CP_WAIT(3); __syncthreads();                       // K0 ready
    pass1_chunk(buf0, qp, 0,  s0, s1, typ, tx, pix0, pix1);

    CP_WAIT(2); __syncthreads();                       // K1 ready, buf0 free
    load_chunk(vp,            sb0, tid, tileX0, tileY0);   // V0 -> g4
    pass1_chunk(buf1, qp, 8,  s0, s1, typ, tx, pix0, pix1);

    CP_WAIT(2); __syncthreads();                       // K2 ready, buf1 free
    load_chunk(vp +  8 * HWs, sb1, tid, tileX0, tileY0);   // V1 -> g5
    pass1_chunk(buf2, qp, 16, s0, s1, typ, tx, pix0, pix1);

    CP_WAIT(2); __syncthreads();                       // K3 ready, buf2 free
    load_chunk(vp + 16 * HWs, sb2, tid, tileX0, tileY0);   // V2 -> g6
    pass1_chunk(buf3, qp, 24, s0, s1, typ, tx, pix0, pix1);

    // ---- reduce packed pairs + mask + scale + softmax (V0..V2 in flight) ----
    const float scale = 0.17677669529663687f; // 1/sqrt(32)
    float p0s[KN], p1s[KN];
    float m0 = -1e30f, m1 = -1e30f;
    #pragma unroll
    for (int n = 0; n < KN; n++) {
        float lo, hi;
        unpack2(s0[n], lo, hi);
        float v0 = lo + hi;
        unpack2(s1[n], lo, hi);
        float v1 = lo + hi;
        const int dy = n / WIN - RAD;
        const int dx = n % WIN - RAD;
        const int gx = x + dx;
        const bool vx = (gx >= 0) & (gx < WS);
        const int gy0 = y0 + dy;
        const int gy1 = y1 + dy;
        const bool ok0 = vx & (gy0 >= 0) & (gy0 < HS);
        const bool ok1 = vx & (gy1 >= 0) & (gy1 < HS);
        p0s[n] = ok0 ? v0 * scale : -1e30f;
        p1s[n] = ok1 ? v1 * scale : -1e30f;
        m0 = fmaxf(m0, p0s[n]);
        m1 = fmaxf(m1, p1s[n]);
    }
    float sum0 = 0.0f, sum1 = 0.0f;
    #pragma unroll
    for (int n = 0; n < KN; n++) {
        p0s[n] = __expf(p0s[n] - m0);
        p1s[n] = __expf(p1s[n] - m1);
        sum0 += p0s[n];
        sum1 += p1s[n];
    }
    const float inv0 = 1.0f / sum0;
    const float inv1 = 1.0f / sum1;
    #pragma unroll
    for (int n = 0; n < KN; n++) {
        float a = p0s[n] * inv0;
        float b = p1s[n] * inv1;
        s0[n] = pack2(a, a);
        s1[n] = pack2(b, b);
    }

    // ---- pass 2, chunk-pipelined ----
    CP_WAIT(2); __syncthreads();                       // V0 ready, buf3 free
    load_chunk(vp + 24 * HWs, sb3, tid, tileX0, tileY0);   // V3 -> g7
    vchunk(buf0, op, 0,  s0, s1, typ, tx, pix0, pix1);

    CP_WAIT(2); __syncthreads();                       // V1 ready
    vchunk(buf1, op, 8,  s0, s1, typ, tx, pix0, pix1);

    CP_WAIT(1); __syncthreads();                       // V2 ready
    vchunk(buf2, op, 16, s0, s1, typ, tx, pix0, pix1);

    CP_WAIT(0); __syncthreads();                       // V3 ready
    vchunk(buf3, op, 24, s0, s1, typ, tx, pix0, pix1);
}

extern "C" void kernel_launch(void* const* d_in, const int* in_sizes, int n_in,
                              void* d_out, int out_size)
{
    const float* q = (const float*)d_in[0];
    const float* k = (const float*)d_in[1];
    const float* v = (const float*)d_in[2];
    float* o = (float*)d_out;

    // Device-function attribute; graph-capture-safe, idempotent.
    cudaFuncSetAttribute(natten2d_kernel,
                         cudaFuncAttributeMaxDynamicSharedMemorySize, SMEM_BYTES);

    const int B = in_sizes[0] / (HEADS * DHEAD * HWs); // 4
    dim3 grid(WS / TILE, HS / TILE, B * HEADS);        // (3, 3, 32) = 288
    dim3 block(NTHR);                                  // 128 linear
    natten2d_kernel<<<grid, block, SMEM_BYTES>>>(q, k, v, o);
}